// round 5
// baseline (speedup 1.0000x reference)
#include <cuda_runtime.h>
#include <cuda_fp16.h>
#include <cstdint>

// ================= problem constants =================
#define FDIM 512
#define EMAX 256
#define X_SCALE 256.0f
#define W_SCALE 4096.0f
#define B_SCALE (X_SCALE * W_SCALE)
// certified bound coefficient: |x·w - xh·wh| <= 2^-10(1+eps)*||x||*||w||
// (fp16 RN splits + fp32 MMA accumulation + norm rounding), with ~28% safety
#define ERR_COEF 0.0013f

// ================= device scratch ====================
__device__ int    g_nactive;
__device__ int    g_npass;
__device__ int    g_eidx[EMAX];
__device__ float  g_ta[EMAX];       // trunc(alpha), 0 in padding
__device__ float  g_bias_s[EMAX];   // bias * B_SCALE
__device__ float  g_borig[EMAX];    // original bias (fixup path)
__device__ float  g_wnorm_s[EMAX];  // ||W_scaled row||_2, 0 in padding
__device__ __half g_Wh[EMAX * FDIM];

// ================= PTX helpers =======================
__device__ __forceinline__ uint32_t smem_u32(const void* p) {
    uint32_t a;
    asm("{ .reg .u64 t; cvta.to.shared.u64 t, %1; cvt.u32.u64 %0, t; }" : "=r"(a) : "l"(p));
    return a;
}
__device__ __forceinline__ void cpa16(uint32_t dst, const void* src) {
    asm volatile("cp.async.cg.shared.global [%0], [%1], 16;" :: "r"(dst), "l"(src) : "memory");
}
__device__ __forceinline__ void cpa_commit() {
    asm volatile("cp.async.commit_group;" ::: "memory");
}
template <int NN> __device__ __forceinline__ void cpa_wait() {
    asm volatile("cp.async.wait_group %0;" :: "n"(NN) : "memory");
}
__device__ __forceinline__ void ldm4(uint32_t& r0, uint32_t& r1, uint32_t& r2, uint32_t& r3,
                                     uint32_t addr) {
    asm volatile("ldmatrix.sync.aligned.m8n8.x4.shared.b16 {%0,%1,%2,%3}, [%4];"
                 : "=r"(r0), "=r"(r1), "=r"(r2), "=r"(r3) : "r"(addr));
}
__device__ __forceinline__ void mma16816(float* c, const uint32_t* a, const uint32_t* b) {
    asm volatile(
        "mma.sync.aligned.m16n8k16.row.col.f32.f16.f16.f32 "
        "{%0,%1,%2,%3}, {%4,%5,%6,%7}, {%8,%9}, {%0,%1,%2,%3};"
        : "+f"(c[0]), "+f"(c[1]), "+f"(c[2]), "+f"(c[3])
        : "r"(a[0]), "r"(a[1]), "r"(a[2]), "r"(a[3]), "r"(b[0]), "r"(b[1]));
}

// ============================================================
// Prep: compaction + scaled-fp16 W hi + per-estimator norms.
// grid = EMAX blocks x 256 threads (redundant compaction, deterministic).
// ============================================================
__global__ __launch_bounds__(256) void pack_kernel(const float* __restrict__ W,
                                                   const float* __restrict__ bias,
                                                   const float* __restrict__ alphas,
                                                   int E) {
    __shared__ int   s_eidx[EMAX];
    __shared__ float s_ta[EMAX];
    __shared__ float s_b[EMAX];
    __shared__ int   wtot[8], woff[8];
    __shared__ int   s_na;
    __shared__ float s_red[8];

    int e = threadIdx.x;
    float ta = 0.f, bi = 0.f;
    int flag = 0;
    if (e < E) {
        ta = truncf(alphas[e]);
        bi = bias[e];
        flag = (ta != 0.f) ? 1 : 0;
    }
    unsigned mask = __ballot_sync(0xffffffffu, flag);
    int lane = e & 31, warp = e >> 5;
    int prefix = __popc(mask & ((1u << lane) - 1u));
    if (lane == 0) wtot[warp] = __popc(mask);
    s_eidx[e] = 0; s_ta[e] = 0.f; s_b[e] = 0.f;
    __syncthreads();
    if (e == 0) {
        int s = 0;
        for (int i = 0; i < 8; i++) { woff[i] = s; s += wtot[i]; }
        s_na = s;
    }
    __syncthreads();
    if (flag) {
        int pos = woff[warp] + prefix;
        s_eidx[pos] = e;
        s_ta[pos] = ta;
        s_b[pos] = bi;
    }
    __syncthreads();

    int na = s_na;
    if (blockIdx.x == 0) {
        g_ta[e]     = s_ta[e];
        g_bias_s[e] = s_b[e] * B_SCALE;
        g_borig[e]  = s_b[e];
        g_eidx[e]   = s_eidx[e];
        if (e == 0) {
            g_nactive = na;
            int np = (na + 127) / 128;
            if (np < 1) np = 1;
            g_npass = np;
        }
    }

    // pack row p (256 threads x 2 floats), accumulate squared norm
    int p = blockIdx.x, t = threadIdx.x;
    float part = 0.f;
    if (p < na) {
        int src = s_eidx[p];
        float2 v = *reinterpret_cast<const float2*>(W + (size_t)src * FDIM + 2 * t);
        float s0 = v.x * W_SCALE, s1 = v.y * W_SCALE;
        *reinterpret_cast<__half2*>(g_Wh + (size_t)p * FDIM + 2 * t) = __floats2half2_rn(s0, s1);
        part = s0 * s0 + s1 * s1;
    } else {
        *reinterpret_cast<__half2*>(g_Wh + (size_t)p * FDIM + 2 * t) = __floats2half2_rn(0.f, 0.f);
    }
#pragma unroll
    for (int o = 16; o; o >>= 1) part += __shfl_xor_sync(0xffffffffu, part, o);
    if (lane == 0) s_red[warp] = part;
    __syncthreads();
    if (t == 0) {
        float s = 0.f;
        for (int i = 0; i < 8; i++) s += s_red[i];
        g_wnorm_s[p] = sqrtf(s);
    }
}

// ============================================================
// Main: 128 rows/CTA, hi-only HMMA + certified fp32 fixup.
// 8 warps = 4(M) x 2(N); warp tile m32 x n64; double-buffered smem.
// ============================================================
#define STR 72                        // smem row stride (halves)
#define OFF_XH0   0
#define OFF_XH1   18432
#define OFF_WH0   36864
#define OFF_WH1   55296
#define OFF_VOTES 73728
#define OFF_XN    74240
#define OFF_SBIAS 74752
#define OFF_STA   75264
#define OFF_SWN   75776
#define OFF_SBO   76288
#define OFF_SEID  76800
#define OFF_WL    77312
#define OFF_CNT   142848
#define SMEM_BYTES 142880

__global__ __launch_bounds__(256, 1) void main_kernel(const float* __restrict__ x,
                                                      const float* __restrict__ Wg,
                                                      float* __restrict__ out,
                                                      int N) {
    extern __shared__ char sm[];
    uint32_t sb = smem_u32(sm);
    float* votes = reinterpret_cast<float*>(sm + OFF_VOTES);
    float* xn2   = reinterpret_cast<float*>(sm + OFF_XN);
    float* sbias = reinterpret_cast<float*>(sm + OFF_SBIAS);
    float* sta   = reinterpret_cast<float*>(sm + OFF_STA);
    float* swn   = reinterpret_cast<float*>(sm + OFF_SWN);
    float* sbo   = reinterpret_cast<float*>(sm + OFF_SBO);
    int*   seid  = reinterpret_cast<int*>(sm + OFF_SEID);
    int*   wl    = reinterpret_cast<int*>(sm + OFF_WL);
    int*   pcnt  = reinterpret_cast<int*>(sm + OFF_CNT);

    const int tid = threadIdx.x, lane = tid & 31, w = tid >> 5;
    const int l4 = lane >> 2, lm = lane & 3, grp = lane >> 3, l8 = lane & 7;
    const int mwarp = w & 3, nwarp = w >> 2;
    const int mbase = mwarp * 32, nbase = nwarp * 64;
    const int rowBase = blockIdx.x * 128;
    const int c4 = tid & 15, rg = tid >> 4;

    if (tid < 128) { votes[tid] = 0.f; xn2[tid] = 0.f; }
    const int na = g_nactive, npass = g_npass;

    float xnorm[8];
#pragma unroll
    for (int i = 0; i < 8; i++) xnorm[i] = 0.f;

    const uint32_t xb[2] = { sb + OFF_XH0, sb + OFF_XH1 };
    const uint32_t wb[2] = { sb + OFF_WH0, sb + OFF_WH1 };

    for (int pass = 0; pass < npass; pass++) {
        if (tid < 128) {
            int e = pass * 128 + tid;
            sbias[tid] = g_bias_s[e];
            sta[tid]   = g_ta[e];
            swn[tid]   = g_wnorm_s[e];
            sbo[tid]   = g_borig[e];
            seid[tid]  = g_eidx[e];
        }
        if (tid == 0) *pcnt = 0;

        int pact = na - pass * 128;
        if (pact > 128) pact = 128;
        if (pact < 0) pact = 0;
        int nl = (pact - nbase + 7) >> 3;
        if (nl < 0) nl = 0;
        if (nl > 8) nl = 8;
        const int nlim = nl;
        const int nnlim = (nlim + 1) >> 1;

        float c[2][8][4];
#pragma unroll
        for (int mi = 0; mi < 2; mi++)
#pragma unroll
            for (int ni = 0; ni < 8; ni++)
#pragma unroll
                for (int j = 0; j < 4; j++) c[mi][ni][j] = 0.f;

        float4 xs[8];
        // ---- prologue: chunk 0 ----
        {
            const float* xp = x + (size_t)rowBase * FDIM + c4 * 4;
#pragma unroll
            for (int i = 0; i < 8; i++) {
                int row = i * 16 + rg;
                xs[i] = (rowBase + row < N)
                          ? *reinterpret_cast<const float4*>(xp + (size_t)row * FDIM)
                          : make_float4(0.f, 0.f, 0.f, 0.f);
            }
#pragma unroll
            for (int jj = 0; jj < 4; jj++) {
                int unit = tid + jj * 256;
                int u8 = unit & 7, r = unit >> 3;
                cpa16(wb[0] + (uint32_t)(r * STR + u8 * 8) * 2,
                      g_Wh + (size_t)(pass * 128 + r) * FDIM + u8 * 8);
            }
            cpa_commit();
#pragma unroll
            for (int i = 0; i < 8; i++) {
                int row = i * 16 + rg;
                if (pass == 0)
                    xnorm[i] += xs[i].x * xs[i].x + xs[i].y * xs[i].y
                              + xs[i].z * xs[i].z + xs[i].w * xs[i].w;
                __half2 h01 = __floats2half2_rn(xs[i].x * X_SCALE, xs[i].y * X_SCALE);
                __half2 h23 = __floats2half2_rn(xs[i].z * X_SCALE, xs[i].w * X_SCALE);
                uint32_t addr = xb[0] + (uint32_t)(row * STR + c4 * 4) * 2;
                asm volatile("st.shared.v2.b32 [%0], {%1,%2};"
                             :: "r"(addr), "r"(*reinterpret_cast<uint32_t*>(&h01)),
                                "r"(*reinterpret_cast<uint32_t*>(&h23)) : "memory");
            }
        }

        for (int kc = 0; kc < 8; kc++) {
            const int cur = kc & 1, nxt = cur ^ 1;
            if (kc < 7) {
                const float* xp = x + (size_t)rowBase * FDIM + (kc + 1) * 64 + c4 * 4;
#pragma unroll
                for (int i = 0; i < 8; i++) {
                    int row = i * 16 + rg;
                    xs[i] = (rowBase + row < N)
                              ? *reinterpret_cast<const float4*>(xp + (size_t)row * FDIM)
                              : make_float4(0.f, 0.f, 0.f, 0.f);
                }
#pragma unroll
                for (int jj = 0; jj < 4; jj++) {
                    int unit = tid + jj * 256;
                    int u8 = unit & 7, r = unit >> 3;
                    cpa16(wb[nxt] + (uint32_t)(r * STR + u8 * 8) * 2,
                          g_Wh + (size_t)(pass * 128 + r) * FDIM + (kc + 1) * 64 + u8 * 8);
                }
                cpa_commit();
                cpa_wait<1>();
            } else {
                cpa_wait<0>();
            }
            __syncthreads();

            // ---- MMAs on current buffers ----
#pragma unroll
            for (int ks = 0; ks < 4; ks++) {
                const int k0 = ks * 16;
                uint32_t a[2][4];
#pragma unroll
                for (int mi = 0; mi < 2; mi++) {
                    int row = mbase + mi * 16 + (grp & 1) * 8 + l8;
                    int ko = k0 + (grp >> 1) * 8;
                    ldm4(a[mi][0], a[mi][1], a[mi][2], a[mi][3],
                         xb[cur] + (uint32_t)(row * STR + ko) * 2);
                }
                uint32_t bfr[8][2];
                for (int nn = 0; nn < nnlim; nn++) {
                    int nrow = nbase + nn * 16 + ((grp >> 1) & 1) * 8 + l8;
                    int ko = k0 + (grp & 1) * 8;
                    ldm4(bfr[2 * nn][0], bfr[2 * nn][1], bfr[2 * nn + 1][0], bfr[2 * nn + 1][1],
                         wb[cur] + (uint32_t)(nrow * STR + ko) * 2);
                }
                for (int ni = 0; ni < nlim; ni++) {
                    mma16816(c[0][ni], a[0], bfr[ni]);
                    mma16816(c[1][ni], a[1], bfr[ni]);
                }
            }

            // ---- convert + store next x chunk (overlaps with other warps' MMAs) ----
            if (kc < 7) {
#pragma unroll
                for (int i = 0; i < 8; i++) {
                    int row = i * 16 + rg;
                    if (pass == 0)
                        xnorm[i] += xs[i].x * xs[i].x + xs[i].y * xs[i].y
                                  + xs[i].z * xs[i].z + xs[i].w * xs[i].w;
                    __half2 h01 = __floats2half2_rn(xs[i].x * X_SCALE, xs[i].y * X_SCALE);
                    __half2 h23 = __floats2half2_rn(xs[i].z * X_SCALE, xs[i].w * X_SCALE);
                    uint32_t addr = xb[nxt] + (uint32_t)(row * STR + c4 * 4) * 2;
                    asm volatile("st.shared.v2.b32 [%0], {%1,%2};"
                                 :: "r"(addr), "r"(*reinterpret_cast<uint32_t*>(&h01)),
                                    "r"(*reinterpret_cast<uint32_t*>(&h23)) : "memory");
                }
            }
            __syncthreads();
        }

        // ---- row norms (pass 0 only; 16 threads/row) ----
        if (pass == 0) {
#pragma unroll
            for (int i = 0; i < 8; i++) atomicAdd(&xn2[i * 16 + rg], xnorm[i]);
        }
        __syncthreads();

        // ---- epilogue: certified margin test + worklist ----
        float xnr[2][2];
#pragma unroll
        for (int mi = 0; mi < 2; mi++)
#pragma unroll
            for (int j = 0; j < 2; j++)
                xnr[mi][j] = X_SCALE * sqrtf(xn2[mbase + mi * 16 + l4 + 8 * j]);

        float acc[2][2] = {{0.f, 0.f}, {0.f, 0.f}};
#pragma unroll
        for (int mi = 0; mi < 2; mi++)
#pragma unroll
            for (int ni = 0; ni < 8; ni++)
#pragma unroll
                for (int cb = 0; cb < 2; cb++) {
                    int e = nbase + ni * 8 + 2 * lm + cb;
                    float ta = sta[e];
                    if (ta == 0.f) continue;
                    float tauw = ERR_COEF * swn[e];
#pragma unroll
                    for (int j = 0; j < 2; j++) {
                        float margin = c[mi][ni][2 * j + cb] + sbias[e];
                        float tau = tauw * xnr[mi][j];
                        if (margin > tau) {
                            acc[mi][j] += ta;
                        } else if (margin >= -tau) {
                            int row = mbase + mi * 16 + l4 + 8 * j;
                            int pos = atomicAdd(pcnt, 1);
                            wl[pos] = (row << 8) | e;
                        }
                    }
                }
#pragma unroll
        for (int mi = 0; mi < 2; mi++) {
            if (acc[mi][0] != 0.f) atomicAdd(&votes[mbase + mi * 16 + l4], acc[mi][0]);
            if (acc[mi][1] != 0.f) atomicAdd(&votes[mbase + mi * 16 + l4 + 8], acc[mi][1]);
        }
        __syncthreads();

        // ---- fixup: exact fp32 dot for uncertain pairs (1 warp / entry) ----
        int total = *pcnt;
        for (int idx = w; idx < total; idx += 8) {
            int ent = wl[idx];
            int row = ent >> 8, e = ent & 255;
            int er = seid[e];
            const float4* xp = reinterpret_cast<const float4*>(x + (size_t)(rowBase + row) * FDIM);
            const float4* wp = reinterpret_cast<const float4*>(Wg + (size_t)er * FDIM);
            float s = 0.f;
#pragma unroll
            for (int jj = 0; jj < 4; jj++) {
                float4 xv = xp[lane + jj * 32];
                float4 wv = wp[lane + jj * 32];
                s += xv.x * wv.x + xv.y * wv.y + xv.z * wv.z + xv.w * wv.w;
            }
#pragma unroll
            for (int o = 16; o; o >>= 1) s += __shfl_xor_sync(0xffffffffu, s, o);
            if (lane == 0) {
                if (s + sbo[e] > 0.f) atomicAdd(&votes[row], sta[e]);
            }
        }
        __syncthreads();
    }

    if (tid < 128) {
        int r = rowBase + tid;
        if (r < N) {
            float v = votes[tid];
            out[r] = (v > 0.f) ? 1.f : ((v < 0.f) ? -1.f : 0.f);
        }
    }
}

// ============================================================
// Launch
// ============================================================
extern "C" void kernel_launch(void* const* d_in, const int* in_sizes, int n_in,
                              void* d_out, int out_size) {
    const float* x      = (const float*)d_in[0];
    const float* W      = (const float*)d_in[1];
    const float* b      = (const float*)d_in[2];
    const float* alphas = (const float*)d_in[3];
    float* out = (float*)d_out;

    int E = in_sizes[2];   // 256
    int N = out_size;      // 131072

    cudaFuncSetAttribute(main_kernel, cudaFuncAttributeMaxDynamicSharedMemorySize,
                         SMEM_BYTES);

    pack_kernel<<<EMAX, 256>>>(W, b, alphas, E);
    int grid = (N + 127) / 128;
    main_kernel<<<grid, 256, SMEM_BYTES>>>(x, W, out, N);
}

// round 6
// speedup vs baseline: 1.0582x; 1.0582x over previous
#include <cuda_runtime.h>
#include <cuda_fp16.h>
#include <cstdint>

// ================= problem constants =================
#define FDIM 512
#define EMAX 256
#define X_SCALE 256.0f
#define W_SCALE 4096.0f
#define B_SCALE (X_SCALE * W_SCALE)
// certified bound: |x·w - xh·wh| <= ERR_COEF * ||x|| * ||w|| (validated R5, rel_err 0.0)
#define ERR_COEF 0.0013f

// ================= device scratch ====================
__device__ int    g_nactive;
__device__ int    g_npass;
__device__ int    g_eidx[EMAX];
__device__ float  g_ta[EMAX];
__device__ float  g_bias_s[EMAX];
__device__ float  g_borig[EMAX];
__device__ float  g_wnorm_s[EMAX];
__device__ __half g_Wh[EMAX * FDIM];

// ================= PTX helpers =======================
__device__ __forceinline__ uint32_t smem_u32(const void* p) {
    uint32_t a;
    asm("{ .reg .u64 t; cvta.to.shared.u64 t, %1; cvt.u32.u64 %0, t; }" : "=r"(a) : "l"(p));
    return a;
}
__device__ __forceinline__ void cpa16(uint32_t dst, const void* src) {
    asm volatile("cp.async.cg.shared.global [%0], [%1], 16;" :: "r"(dst), "l"(src) : "memory");
}
__device__ __forceinline__ void cpa_commit() {
    asm volatile("cp.async.commit_group;" ::: "memory");
}
template <int NN> __device__ __forceinline__ void cpa_wait() {
    asm volatile("cp.async.wait_group %0;" :: "n"(NN) : "memory");
}
__device__ __forceinline__ void ldm4(uint32_t& r0, uint32_t& r1, uint32_t& r2, uint32_t& r3,
                                     uint32_t addr) {
    asm volatile("ldmatrix.sync.aligned.m8n8.x4.shared.b16 {%0,%1,%2,%3}, [%4];"
                 : "=r"(r0), "=r"(r1), "=r"(r2), "=r"(r3) : "r"(addr));
}
__device__ __forceinline__ void mma16816(float* c, const uint32_t* a, const uint32_t* b) {
    asm volatile(
        "mma.sync.aligned.m16n8k16.row.col.f32.f16.f16.f32 "
        "{%0,%1,%2,%3}, {%4,%5,%6,%7}, {%8,%9}, {%0,%1,%2,%3};"
        : "+f"(c[0]), "+f"(c[1]), "+f"(c[2]), "+f"(c[3])
        : "r"(a[0]), "r"(a[1]), "r"(a[2]), "r"(a[3]), "r"(b[0]), "r"(b[1]));
}

// ============================================================
// Prep: compaction + scaled-fp16 W hi + per-estimator norms.
// ============================================================
__global__ __launch_bounds__(256) void pack_kernel(const float* __restrict__ W,
                                                   const float* __restrict__ bias,
                                                   const float* __restrict__ alphas,
                                                   int E) {
    __shared__ int   s_eidx[EMAX];
    __shared__ float s_ta[EMAX];
    __shared__ float s_b[EMAX];
    __shared__ int   wtot[8], woff[8];
    __shared__ int   s_na;
    __shared__ float s_red[8];

    int e = threadIdx.x;
    float ta = 0.f, bi = 0.f;
    int flag = 0;
    if (e < E) {
        ta = truncf(alphas[e]);
        bi = bias[e];
        flag = (ta != 0.f) ? 1 : 0;
    }
    unsigned mask = __ballot_sync(0xffffffffu, flag);
    int lane = e & 31, warp = e >> 5;
    int prefix = __popc(mask & ((1u << lane) - 1u));
    if (lane == 0) wtot[warp] = __popc(mask);
    s_eidx[e] = 0; s_ta[e] = 0.f; s_b[e] = 0.f;
    __syncthreads();
    if (e == 0) {
        int s = 0;
        for (int i = 0; i < 8; i++) { woff[i] = s; s += wtot[i]; }
        s_na = s;
    }
    __syncthreads();
    if (flag) {
        int pos = woff[warp] + prefix;
        s_eidx[pos] = e;
        s_ta[pos] = ta;
        s_b[pos] = bi;
    }
    __syncthreads();

    int na = s_na;
    if (blockIdx.x == 0) {
        g_ta[e]     = s_ta[e];
        g_bias_s[e] = s_b[e] * B_SCALE;
        g_borig[e]  = s_b[e];
        g_eidx[e]   = s_eidx[e];
        if (e == 0) {
            g_nactive = na;
            int np = (na + 127) / 128;
            if (np < 1) np = 1;
            g_npass = np;
        }
    }

    int p = blockIdx.x, t = threadIdx.x;
    float part = 0.f;
    if (p < na) {
        int src = s_eidx[p];
        float2 v = *reinterpret_cast<const float2*>(W + (size_t)src * FDIM + 2 * t);
        float s0 = v.x * W_SCALE, s1 = v.y * W_SCALE;
        *reinterpret_cast<__half2*>(g_Wh + (size_t)p * FDIM + 2 * t) = __floats2half2_rn(s0, s1);
        part = s0 * s0 + s1 * s1;
    } else {
        *reinterpret_cast<__half2*>(g_Wh + (size_t)p * FDIM + 2 * t) = __floats2half2_rn(0.f, 0.f);
    }
#pragma unroll
    for (int o = 16; o; o >>= 1) part += __shfl_xor_sync(0xffffffffu, part, o);
    if (lane == 0) s_red[warp] = part;
    __syncthreads();
    if (t == 0) {
        float s = 0.f;
        for (int i = 0; i < 8; i++) s += s_red[i];
        g_wnorm_s[p] = sqrtf(s);
    }
}

// ============================================================
// Main: 128 rows/CTA, hi-only HMMA + certified fp32 fixup.
// 8 warps = 4(M) x 2(N); warp tile m32 x n64; double-buffered smem.
// ALL fragment loops are compile-time unrolled; N-tile skipping is
// warp-uniform predication around statically-indexed ops.
// ============================================================
#define STR 72
#define OFF_XH0   0
#define OFF_XH1   18432
#define OFF_WH0   36864
#define OFF_WH1   55296
#define OFF_VOTES 73728
#define OFF_XN    74240
#define OFF_SBIAS 74752
#define OFF_STA   75264
#define OFF_SWN   75776
#define OFF_SBO   76288
#define OFF_SEID  76800
#define OFF_WL    77312
#define WLCAP     4096
#define OFF_CNT   (OFF_WL + WLCAP * 4)
#define SMEM_BYTES (OFF_CNT + 32)

__global__ __launch_bounds__(256, 1) void main_kernel(const float* __restrict__ x,
                                                      const float* __restrict__ Wg,
                                                      float* __restrict__ out,
                                                      int N) {
    extern __shared__ char sm[];
    uint32_t sb = smem_u32(sm);
    float* votes = reinterpret_cast<float*>(sm + OFF_VOTES);
    float* xn2   = reinterpret_cast<float*>(sm + OFF_XN);
    float* sbias = reinterpret_cast<float*>(sm + OFF_SBIAS);
    float* sta   = reinterpret_cast<float*>(sm + OFF_STA);
    float* swn   = reinterpret_cast<float*>(sm + OFF_SWN);
    float* sbo   = reinterpret_cast<float*>(sm + OFF_SBO);
    int*   seid  = reinterpret_cast<int*>(sm + OFF_SEID);
    int*   wl    = reinterpret_cast<int*>(sm + OFF_WL);
    int*   pcnt  = reinterpret_cast<int*>(sm + OFF_CNT);

    const int tid = threadIdx.x, lane = tid & 31, w = tid >> 5;
    const int l4 = lane >> 2, lm = lane & 3, grp = lane >> 3, l8 = lane & 7;
    const int mwarp = w & 3, nwarp = w >> 2;
    const int mbase = mwarp * 32, nbase = nwarp * 64;
    const int rowBase = blockIdx.x * 128;
    const int c4 = tid & 15, rg = tid >> 4;

    if (tid < 128) { votes[tid] = 0.f; xn2[tid] = 0.f; }
    const int na = g_nactive, npass = g_npass;

    float xnorm[8];
#pragma unroll
    for (int i = 0; i < 8; i++) xnorm[i] = 0.f;

    const uint32_t xb[2] = { sb + OFF_XH0, sb + OFF_XH1 };
    const uint32_t wb[2] = { sb + OFF_WH0, sb + OFF_WH1 };

    for (int pass = 0; pass < npass; pass++) {
        if (tid < 128) {
            int e = pass * 128 + tid;
            sbias[tid] = g_bias_s[e];
            sta[tid]   = g_ta[e];
            swn[tid]   = g_wnorm_s[e];
            sbo[tid]   = g_borig[e];
            seid[tid]  = g_eidx[e];
        }
        if (tid == 0) *pcnt = 0;

        int pact = na - pass * 128;
        if (pact > 128) pact = 128;
        if (pact < 0) pact = 0;

        float c[2][8][4];
#pragma unroll
        for (int mi = 0; mi < 2; mi++)
#pragma unroll
            for (int ni = 0; ni < 8; ni++)
#pragma unroll
                for (int j = 0; j < 4; j++) c[mi][ni][j] = 0.f;

        float4 xs[8];
        // ---- prologue: chunk 0 ----
        {
            const float* xp = x + (size_t)rowBase * FDIM + c4 * 4;
#pragma unroll
            for (int i = 0; i < 8; i++) {
                int row = i * 16 + rg;
                xs[i] = (rowBase + row < N)
                          ? *reinterpret_cast<const float4*>(xp + (size_t)row * FDIM)
                          : make_float4(0.f, 0.f, 0.f, 0.f);
            }
#pragma unroll
            for (int jj = 0; jj < 4; jj++) {
                int unit = tid + jj * 256;
                int u8 = unit & 7, r = unit >> 3;
                cpa16(wb[0] + (uint32_t)(r * STR + u8 * 8) * 2,
                      g_Wh + (size_t)(pass * 128 + r) * FDIM + u8 * 8);
            }
            cpa_commit();
#pragma unroll
            for (int i = 0; i < 8; i++) {
                int row = i * 16 + rg;
                if (pass == 0)
                    xnorm[i] += xs[i].x * xs[i].x + xs[i].y * xs[i].y
                              + xs[i].z * xs[i].z + xs[i].w * xs[i].w;
                __half2 h01 = __floats2half2_rn(xs[i].x * X_SCALE, xs[i].y * X_SCALE);
                __half2 h23 = __floats2half2_rn(xs[i].z * X_SCALE, xs[i].w * X_SCALE);
                uint32_t addr = xb[0] + (uint32_t)(row * STR + c4 * 4) * 2;
                asm volatile("st.shared.v2.b32 [%0], {%1,%2};"
                             :: "r"(addr), "r"(*reinterpret_cast<uint32_t*>(&h01)),
                                "r"(*reinterpret_cast<uint32_t*>(&h23)) : "memory");
            }
        }

        for (int kc = 0; kc < 8; kc++) {
            const int cur = kc & 1, nxt = cur ^ 1;
            if (kc < 7) {
                const float* xp = x + (size_t)rowBase * FDIM + (kc + 1) * 64 + c4 * 4;
#pragma unroll
                for (int i = 0; i < 8; i++) {
                    int row = i * 16 + rg;
                    xs[i] = (rowBase + row < N)
                              ? *reinterpret_cast<const float4*>(xp + (size_t)row * FDIM)
                              : make_float4(0.f, 0.f, 0.f, 0.f);
                }
#pragma unroll
                for (int jj = 0; jj < 4; jj++) {
                    int unit = tid + jj * 256;
                    int u8 = unit & 7, r = unit >> 3;
                    cpa16(wb[nxt] + (uint32_t)(r * STR + u8 * 8) * 2,
                          g_Wh + (size_t)(pass * 128 + r) * FDIM + (kc + 1) * 64 + u8 * 8);
                }
                cpa_commit();
                cpa_wait<1>();
            } else {
                cpa_wait<0>();
            }
            __syncthreads();

            // ---- MMAs on current buffers (fully static; warp-uniform guards) ----
#pragma unroll
            for (int ks = 0; ks < 4; ks++) {
                const int k0 = ks * 16;
                uint32_t a[2][4];
#pragma unroll
                for (int mi = 0; mi < 2; mi++) {
                    int row = mbase + mi * 16 + (grp & 1) * 8 + l8;
                    int ko = k0 + (grp >> 1) * 8;
                    ldm4(a[mi][0], a[mi][1], a[mi][2], a[mi][3],
                         xb[cur] + (uint32_t)(row * STR + ko) * 2);
                }
                uint32_t bfr[8][2];
#pragma unroll
                for (int nn = 0; nn < 4; nn++) {
                    if (nbase + nn * 16 < pact) {
                        int nrow = nbase + nn * 16 + ((grp >> 1) & 1) * 8 + l8;
                        int ko = k0 + (grp & 1) * 8;
                        ldm4(bfr[2 * nn][0], bfr[2 * nn][1],
                             bfr[2 * nn + 1][0], bfr[2 * nn + 1][1],
                             wb[cur] + (uint32_t)(nrow * STR + ko) * 2);
                    }
                }
#pragma unroll
                for (int ni = 0; ni < 8; ni++) {
                    if (nbase + ni * 8 < pact) {
                        mma16816(c[0][ni], a[0], bfr[ni]);
                        mma16816(c[1][ni], a[1], bfr[ni]);
                    }
                }
            }

            if (kc < 7) {
#pragma unroll
                for (int i = 0; i < 8; i++) {
                    int row = i * 16 + rg;
                    if (pass == 0)
                        xnorm[i] += xs[i].x * xs[i].x + xs[i].y * xs[i].y
                                  + xs[i].z * xs[i].z + xs[i].w * xs[i].w;
                    __half2 h01 = __floats2half2_rn(xs[i].x * X_SCALE, xs[i].y * X_SCALE);
                    __half2 h23 = __floats2half2_rn(xs[i].z * X_SCALE, xs[i].w * X_SCALE);
                    uint32_t addr = xb[nxt] + (uint32_t)(row * STR + c4 * 4) * 2;
                    asm volatile("st.shared.v2.b32 [%0], {%1,%2};"
                                 :: "r"(addr), "r"(*reinterpret_cast<uint32_t*>(&h01)),
                                    "r"(*reinterpret_cast<uint32_t*>(&h23)) : "memory");
                }
            }
            __syncthreads();
        }

        if (pass == 0) {
#pragma unroll
            for (int i = 0; i < 8; i++) atomicAdd(&xn2[i * 16 + rg], xnorm[i]);
        }
        __syncthreads();

        // ---- epilogue: certified margin test + worklist ----
        float xnr[2][2];
#pragma unroll
        for (int mi = 0; mi < 2; mi++)
#pragma unroll
            for (int j = 0; j < 2; j++)
                xnr[mi][j] = X_SCALE * sqrtf(xn2[mbase + mi * 16 + l4 + 8 * j]);

        float acc[2][2] = {{0.f, 0.f}, {0.f, 0.f}};
#pragma unroll
        for (int mi = 0; mi < 2; mi++)
#pragma unroll
            for (int ni = 0; ni < 8; ni++) {
                if (nbase + ni * 8 >= pact) continue;
#pragma unroll
                for (int cb = 0; cb < 2; cb++) {
                    int e = nbase + ni * 8 + 2 * lm + cb;
                    float ta = sta[e];
                    if (ta == 0.f) continue;
                    float tauw = ERR_COEF * swn[e];
#pragma unroll
                    for (int j = 0; j < 2; j++) {
                        float margin = c[mi][ni][2 * j + cb] + sbias[e];
                        float tau = tauw * xnr[mi][j];
                        if (margin > tau) {
                            acc[mi][j] += ta;
                        } else if (margin >= -tau) {
                            int row = mbase + mi * 16 + l4 + 8 * j;
                            int pos = atomicAdd(pcnt, 1);
                            if (pos < WLCAP) {
                                wl[pos] = (row << 8) | e;
                            } else {
                                // overflow fallback: exact dot inline (exceedingly rare)
                                const float* xp = x + (size_t)(rowBase + row) * FDIM;
                                const float* wp = Wg + (size_t)seid[e] * FDIM;
                                float s = 0.f;
                                for (int kk = 0; kk < FDIM; kk++) s += xp[kk] * wp[kk];
                                if (s + sbo[e] > 0.f) atomicAdd(&votes[row], ta);
                            }
                        }
                    }
                }
            }
#pragma unroll
        for (int mi = 0; mi < 2; mi++) {
            if (acc[mi][0] != 0.f) atomicAdd(&votes[mbase + mi * 16 + l4], acc[mi][0]);
            if (acc[mi][1] != 0.f) atomicAdd(&votes[mbase + mi * 16 + l4 + 8], acc[mi][1]);
        }
        __syncthreads();

        // ---- fixup: exact fp32 dot per worklist entry (1 warp / entry) ----
        int total = *pcnt;
        if (total > WLCAP) total = WLCAP;
        for (int idx = w; idx < total; idx += 8) {
            int ent = wl[idx];
            int row = ent >> 8, e = ent & 255;
            int er = seid[e];
            const float4* xp = reinterpret_cast<const float4*>(x + (size_t)(rowBase + row) * FDIM);
            const float4* wp = reinterpret_cast<const float4*>(Wg + (size_t)er * FDIM);
            float s = 0.f;
#pragma unroll
            for (int jj = 0; jj < 4; jj++) {
                float4 xv = xp[lane + jj * 32];
                float4 wv = wp[lane + jj * 32];
                s += xv.x * wv.x + xv.y * wv.y + xv.z * wv.z + xv.w * wv.w;
            }
#pragma unroll
            for (int o = 16; o; o >>= 1) s += __shfl_xor_sync(0xffffffffu, s, o);
            if (lane == 0) {
                if (s + sbo[e] > 0.f) atomicAdd(&votes[row], sta[e]);
            }
        }
        __syncthreads();
    }

    if (tid < 128) {
        int r = rowBase + tid;
        if (r < N) {
            float v = votes[tid];
            out[r] = (v > 0.f) ? 1.f : ((v < 0.f) ? -1.f : 0.f);
        }
    }
}

// ============================================================
// Launch
// ============================================================
extern "C" void kernel_launch(void* const* d_in, const int* in_sizes, int n_in,
                              void* d_out, int out_size) {
    const float* x      = (const float*)d_in[0];
    const float* W      = (const float*)d_in[1];
    const float* b      = (const float*)d_in[2];
    const float* alphas = (const float*)d_in[3];
    float* out = (float*)d_out;

    int E = in_sizes[2];   // 256
    int N = out_size;      // 131072

    cudaFuncSetAttribute(main_kernel, cudaFuncAttributeMaxDynamicSharedMemorySize,
                         SMEM_BYTES);

    pack_kernel<<<EMAX, 256>>>(W, b, alphas, E);
    int grid = (N + 127) / 128;
    main_kernel<<<grid, 256, SMEM_BYTES>>>(x, W, out, N);
}